// round 16
// baseline (speedup 1.0000x reference)
#include <cuda_runtime.h>
#include <cuda_bf16.h>
#include <cstdint>

#define B_   8
#define C_   256
#define CQ_  32
#define H_   128
#define W_   128
#define HW_  (H_*W_)

typedef unsigned long long u64;

// ---------------- scratch ----------------------------------------------------
__device__ float g_qc [(size_t)B_*HW_*CQ_];   // [b, p, c]
__device__ float g_kc [(size_t)B_*HW_*CQ_];   // [b, p, c]
__device__ float g_v  [(size_t)B_*C_*HW_];    // [b, c, h, w]
__device__ float g_vt [(size_t)B_*C_*HW_];    // [b, c, w, h]
__device__ float g_att[(size_t)B_*H_*W_*256]; // [b,h,w, 0:128=H, 128:256=W]
__device__ float g_oht[(size_t)B_*C_*HW_];    // outH transposed: [b,c,w,h]
__device__ float g_ow [(size_t)B_*C_*HW_];    // outW: [b,c,h,w]

#define NEGF (__int_as_float(0xff800000))

// ---------------- bf16 split + mma helpers ------------------------------------
// smem tile format: per k-pair (2 elems): {hi0hi1 (4B), lo0lo1 (4B)} interleaved.
// byte offset of k index g inside a row = g*4 (pair g/2 at (g/2)*8).
__device__ __forceinline__ void st_split(char* dst, float4 v) {
    __nv_bfloat16 h0 = __float2bfloat16(v.x), h1 = __float2bfloat16(v.y);
    __nv_bfloat16 h2 = __float2bfloat16(v.z), h3 = __float2bfloat16(v.w);
    __nv_bfloat16 l0 = __float2bfloat16(v.x - __bfloat162float(h0));
    __nv_bfloat16 l1 = __float2bfloat16(v.y - __bfloat162float(h1));
    __nv_bfloat16 l2 = __float2bfloat16(v.z - __bfloat162float(h2));
    __nv_bfloat16 l3 = __float2bfloat16(v.w - __bfloat162float(h3));
    uint4 w;
    w.x = ((unsigned)__bfloat16_as_ushort(h1) << 16) | __bfloat16_as_ushort(h0);
    w.y = ((unsigned)__bfloat16_as_ushort(l1) << 16) | __bfloat16_as_ushort(l0);
    w.z = ((unsigned)__bfloat16_as_ushort(h3) << 16) | __bfloat16_as_ushort(h2);
    w.w = ((unsigned)__bfloat16_as_ushort(l3) << 16) | __bfloat16_as_ushort(l2);
    *(uint4*)dst = w;
}
__device__ __forceinline__ void mma16816(float c[4], const unsigned a[4], const unsigned b[2]) {
    asm volatile(
        "mma.sync.aligned.m16n8k16.row.col.f32.bf16.bf16.f32 "
        "{%0,%1,%2,%3}, {%4,%5,%6,%7}, {%8,%9}, {%0,%1,%2,%3};"
        : "+f"(c[0]), "+f"(c[1]), "+f"(c[2]), "+f"(c[3])
        : "r"(a[0]), "r"(a[1]), "r"(a[2]), "r"(a[3]), "r"(b[0]), "r"(b[1]));
}

#define RSK   544                          // row stride bytes, K=128 (64 pairs*8 + 32 pad)
#define RSQ   160                          // row stride bytes, K=32  (16 pairs*8 + 32 pad)

// k4: V tile 64 rows, A tile 128 rows
#define K4_V  0
#define K4_A  (64 * RSK)                   // 34816
#define SMEM_K4 (64 * RSK + 128 * RSK)     // 104448
// k1 v: W 128 rows, X 64 rows
#define K1_W  0
#define K1_X  (128 * RSK)                  // 69632
#define SMEM_K1 (128 * RSK + 64 * RSK)     // 104448
// k1 q/k: W 32 rows, X 128 rows (total 87040 <= SMEM_K1)
#define QP_W  0
#define QP_X  (32 * RSK)                   // 17408
// eH/eW: Q 128 rows, K 128 rows (RSQ)
#define E_Q   0
#define E_K   (128 * RSQ)                  // 20480
#define SMEM_E  (128 * 132 * 4)            // 67584 (Es stage; > 2*20480)

// A frags (m16 rows rb..rb+15, k cols k0..k0+15), hi+lo in one u64 per pair
__device__ __forceinline__ void ldfragA2(const char* sm, int off, int rb, int k0,
                                         int gid, int tig, int rs,
                                         unsigned aH[4], unsigned aL[4]) {
    const char* base = sm + off + (rb + gid) * rs + k0 * 4 + tig * 8;
    u64 w0 = *(const u64*)(base);
    u64 w1 = *(const u64*)(base + 8 * rs);
    u64 w2 = *(const u64*)(base + 32);
    u64 w3 = *(const u64*)(base + 8 * rs + 32);
    aH[0] = (unsigned)w0; aL[0] = (unsigned)(w0 >> 32);
    aH[1] = (unsigned)w1; aL[1] = (unsigned)(w1 >> 32);
    aH[2] = (unsigned)w2; aL[2] = (unsigned)(w2 >> 32);
    aH[3] = (unsigned)w3; aL[3] = (unsigned)(w3 >> 32);
}
__device__ __forceinline__ void ldfragB2(const char* sm, int off, int xb, int k0,
                                         int gid, int tig, int rs,
                                         unsigned bH[2], unsigned bL[2]) {
    const char* base = sm + off + (xb + gid) * rs + k0 * 4 + tig * 8;
    u64 w0 = *(const u64*)(base);
    u64 w1 = *(const u64*)(base + 32);
    bH[0] = (unsigned)w0; bL[0] = (unsigned)(w0 >> 32);
    bH[1] = (unsigned)w1; bL[1] = (unsigned)(w1 >> 32);
}

// ---------------- exact 64th-largest, 2 rows, packed counts + early exit -----
__device__ __forceinline__ void topk64x2(const float v[2][4], float thr[2])
{
    unsigned keys[2][4];
    #pragma unroll
    for (int r = 0; r < 2; ++r)
        #pragma unroll
        for (int j = 0; j < 4; ++j) {
            unsigned u = __float_as_uint(v[r][j]);
            keys[r][j] = (u & 0x80000000u) ? ~u : (u | 0x80000000u);
        }
    unsigned prefix[2] = {0, 0};
    unsigned need[2]   = {64, 64};
    unsigned cand[2]   = {128, 128};
    int      ebit[2]   = {0, 0};
    unsigned done = 0;

    for (int bit = 31; bit >= 0; --bit) {
        unsigned packed = 0;
        #pragma unroll
        for (int r = 0; r < 2; ++r) {
            if (!(done & (1u << r))) {
                unsigned want = (prefix[r] >> bit) | 1u;
                unsigned c = 0;
                #pragma unroll
                for (int j = 0; j < 4; ++j)
                    c += (unsigned)((keys[r][j] >> bit) == want);
                packed += c << (8 * r);
            }
        }
        packed = __reduce_add_sync(0xffffffffu, packed);
        #pragma unroll
        for (int r = 0; r < 2; ++r) {
            if (!(done & (1u << r))) {
                unsigned c = (packed >> (8 * r)) & 255u;
                if (c >= need[r]) { prefix[r] |= 1u << bit; cand[r] = c; }
                else              { need[r] -= c; cand[r] -= c; }
                if (cand[r] == need[r]) { done |= 1u << r; ebit[r] = bit; }
            }
        }
        if (done == 3u) break;
    }
    #pragma unroll
    for (int r = 0; r < 2; ++r) {
        unsigned key;
        if (done & (1u << r)) {
            unsigned mn = 0xFFFFFFFFu;
            #pragma unroll
            for (int j = 0; j < 4; ++j) {
                bool match = (((keys[r][j] ^ prefix[r]) >> ebit[r]) == 0);
                unsigned cand_k = match ? keys[r][j] : 0xFFFFFFFFu;
                mn = cand_k < mn ? cand_k : mn;
            }
            key = __reduce_min_sync(0xffffffffu, mn);
        } else {
            key = prefix[r];
        }
        unsigned u = (key & 0x80000000u) ? (key ^ 0x80000000u) : ~key;
        thr[r] = __uint_as_float(u);
    }
}

// ---------------- q/k projection via mma (512 threads) ------------------------
__device__ __forceinline__ void proj_qk_mma_body(
    const float* __restrict__ X, const float* __restrict__ Wm,
    const float* __restrict__ bias, float* __restrict__ Y,
    int b, int p0, char* sm)
{
    const int t = threadIdx.x, wid = t >> 5, lane = t & 31;
    const int gid = lane >> 2, tig = lane & 3;
    const int wr = wid & 1, wc = wid >> 1;    // warp tile: 16 o x 16 p
    float acc[2][4] = {};
    for (int kc = 0; kc < C_; kc += 128) {
        #pragma unroll
        for (int i = 0; i < 2; ++i) {         // W: 1024 float4
            int idx = t + i * 512;
            int o = idx >> 5, c4 = (idx & 31) * 4;
            st_split(sm + QP_W + o * RSK + c4 * 4,
                     *(const float4*)(Wm + (size_t)o * C_ + kc + c4));
        }
        const float* Xb = X + ((size_t)b * C_ + kc) * HW_ + p0;
        #pragma unroll
        for (int i = 0; i < 8; ++i) {         // X: 4096 packs of 4c
            int idx = t + i * 512;
            int c4 = (idx >> 7) * 4, p = idx & 127;
            float4 xv;
            xv.x = Xb[(size_t)(c4 + 0) * HW_ + p];
            xv.y = Xb[(size_t)(c4 + 1) * HW_ + p];
            xv.z = Xb[(size_t)(c4 + 2) * HW_ + p];
            xv.w = Xb[(size_t)(c4 + 3) * HW_ + p];
            st_split(sm + QP_X + p * RSK + c4 * 4, xv);
        }
        __syncthreads();
        #pragma unroll
        for (int ks = 0; ks < 8; ++ks) {
            const int k0 = ks * 16;
            unsigned aH[4], aL[4];
            ldfragA2(sm, QP_W, wr * 16, k0, gid, tig, RSK, aH, aL);
            #pragma unroll
            for (int j = 0; j < 2; ++j) {
                unsigned bH[2], bL[2];
                ldfragB2(sm, QP_X, wc * 16 + j * 8, k0, gid, tig, RSK, bH, bL);
                mma16816(acc[j], aH, bH);
                mma16816(acc[j], aH, bL);
                mma16816(acc[j], aL, bH);
            }
        }
        __syncthreads();
    }
    float* stage = (float*)sm;                // [128 p][33 o]
    #pragma unroll
    for (int j = 0; j < 2; ++j) {
        int row = wr * 16 + gid;              // o
        int col = wc * 16 + j * 8 + tig * 2;  // p
        stage[col * 33 + row]           = acc[j][0];
        stage[(col + 1) * 33 + row]     = acc[j][1];
        stage[col * 33 + row + 8]       = acc[j][2];
        stage[(col + 1) * 33 + row + 8] = acc[j][3];
    }
    __syncthreads();
    #pragma unroll
    for (int i = 0; i < 2; ++i) {
        int idx = t + i * 512;                // 1024 float4
        int p = idx >> 3, o4 = (idx & 7) * 4;
        float4 r;
        r.x = stage[p * 33 + o4 + 0] + bias[o4 + 0];
        r.y = stage[p * 33 + o4 + 1] + bias[o4 + 1];
        r.z = stage[p * 33 + o4 + 2] + bias[o4 + 2];
        r.w = stage[p * 33 + o4 + 3] + bias[o4 + 3];
        *(float4*)(Y + ((size_t)b * HW_ + p0 + p) * CQ_ + o4) = r;
    }
}

// ---------------- v projection via mma, p-tile 64 ----------------------------
__device__ __forceinline__ void proj_v_mma_body(
    const float* __restrict__ x2, const float* __restrict__ Wv,
    const float* __restrict__ bv, int id, char* sm)
{
    const int b = id >> 9, o0 = ((id >> 8) & 1) * 128, p0 = (id & 255) * 64;
    const int t = threadIdx.x, wid = t >> 5, lane = t & 31;
    const int gid = lane >> 2, tig = lane & 3;
    const int wr = wid & 3, wc = wid >> 2;    // warp tile: 32 o x 16 p

    float acc[2][2][4] = {};
    for (int kc = 0; kc < C_; kc += 128) {
        #pragma unroll
        for (int i = 0; i < 8; ++i) {
            int idx = t + i * 512;
            int o = idx >> 5, c4 = (idx & 31) * 4;
            st_split(sm + K1_W + o * RSK + c4 * 4,
                     *(const float4*)(Wv + (size_t)(o0 + o) * C_ + kc + c4));
        }
        const float* Xb = x2 + ((size_t)b * C_ + kc) * HW_ + p0;
        #pragma unroll
        for (int i = 0; i < 4; ++i) {
            int idx = t + i * 512;
            int c4 = (idx >> 6) * 4, p = idx & 63;
            float4 xv;
            xv.x = Xb[(size_t)(c4 + 0) * HW_ + p];
            xv.y = Xb[(size_t)(c4 + 1) * HW_ + p];
            xv.z = Xb[(size_t)(c4 + 2) * HW_ + p];
            xv.w = Xb[(size_t)(c4 + 3) * HW_ + p];
            st_split(sm + K1_X + p * RSK + c4 * 4, xv);
        }
        __syncthreads();
        #pragma unroll
        for (int ks = 0; ks < 8; ++ks) {
            const int k0 = ks * 16;
            #pragma unroll
            for (int i = 0; i < 2; ++i) {
                unsigned aH[4], aL[4];
                ldfragA2(sm, K1_W, wr * 32 + i * 16, k0, gid, tig, RSK, aH, aL);
                #pragma unroll
                for (int j = 0; j < 2; ++j) {
                    unsigned bH[2], bL[2];
                    ldfragB2(sm, K1_X, wc * 16 + j * 8, k0, gid, tig, RSK, bH, bL);
                    mma16816(acc[i][j], aH, bH);
                    mma16816(acc[i][j], aH, bL);
                    mma16816(acc[i][j], aL, bH);
                }
            }
        }
        __syncthreads();
    }
    float* stage = (float*)sm;     // [128 o][68 p]
    #pragma unroll
    for (int i = 0; i < 2; ++i)
        #pragma unroll
        for (int j = 0; j < 2; ++j) {
            int row = wr * 32 + i * 16 + gid;
            int col = wc * 16 + j * 8 + tig * 2;
            *(float2*)&stage[row * 68 + col]       = make_float2(acc[i][j][0], acc[i][j][1]);
            *(float2*)&stage[(row + 8) * 68 + col] = make_float2(acc[i][j][2], acc[i][j][3]);
        }
    __syncthreads();
    #pragma unroll
    for (int i = 0; i < 4; ++i) {
        int idx = t + i * 512;
        int o = idx >> 4, p4 = (idx & 15) * 4;
        float bvv = bv[o0 + o];
        float2 u2 = *(float2*)&stage[o * 68 + p4];
        float2 w2 = *(float2*)&stage[o * 68 + p4 + 2];
        *(float4*)(g_v + ((size_t)b * C_ + o0 + o) * HW_ + p0 + p4) =
            make_float4(u2.x + bvv, u2.y + bvv, w2.x + bvv, w2.y + bvv);
    }
}

// ---------------- K1: ALL projections fused (512 threads, 2 CTAs/SM) ---------
__global__ void __launch_bounds__(512, 2) k1_proj(
    const float* __restrict__ x1, const float* __restrict__ x2,
    const float* __restrict__ Wq, const float* __restrict__ bq,
    const float* __restrict__ Wk, const float* __restrict__ bk,
    const float* __restrict__ Wv, const float* __restrict__ bv)
{
    extern __shared__ __align__(16) char smc[];
    const int id = blockIdx.x;
    if (id < 4096) {
        proj_v_mma_body(x2, Wv, bv, id, smc);
    } else if (id < 5120) {
        int r = id - 4096;
        proj_qk_mma_body(x1, Wq, bq, g_qc, r >> 7, (r & 127) * 128, smc);
    } else {
        int r = id - 5120;
        proj_qk_mma_body(x2, Wk, bk, g_kc, r >> 7, (r & 127) * 128, smc);
    }
}

// ---------------- QK score tile via mma ----------------------------------------
__device__ __forceinline__ void qk_mma(
    const float* __restrict__ qb, const float* __restrict__ kb, size_t rowstride,
    char* sm, float acc[2][4][4])
{
    const int t = threadIdx.x, wid = t >> 5, lane = t & 31;
    const int gid = lane >> 2, tig = lane & 3;
    const int wr = wid & 3, wc = wid >> 2;
    #pragma unroll
    for (int i = 0; i < 2; ++i) {
        int idx = t + i * 512;
        int r = idx >> 3, c4 = (idx & 7) * 4;
        size_t off = (size_t)r * rowstride + c4;
        st_split(sm + E_Q + r * RSQ + c4 * 4, *(const float4*)(qb + off));
        st_split(sm + E_K + r * RSQ + c4 * 4, *(const float4*)(kb + off));
    }
    __syncthreads();
    #pragma unroll
    for (int ks = 0; ks < 2; ++ks) {
        const int k0 = ks * 16;
        #pragma unroll
        for (int i = 0; i < 2; ++i) {
            unsigned aH[4], aL[4];
            ldfragA2(sm, E_Q, wr * 32 + i * 16, k0, gid, tig, RSQ, aH, aL);
            #pragma unroll
            for (int j = 0; j < 4; ++j) {
                unsigned bH[2], bL[2];
                ldfragB2(sm, E_K, wc * 32 + j * 8, k0, gid, tig, RSQ, bH, bL);
                mma16816(acc[i][j], aH, bH);
                mma16816(acc[i][j], aH, bL);
                mma16816(acc[i][j], aL, bH);
            }
        }
    }
    __syncthreads();
}

// ---------------- eH body (512 threads, mma + topk) ---------------------------
__device__ __forceinline__ void eH_body(int w, int b, char* sm)
{
    const int t = threadIdx.x, wid5 = t >> 5, lane = t & 31;
    const int gid = lane >> 2, tig = lane & 3;
    const int wr = wid5 & 3, wc = wid5 >> 2;
    float acc[2][4][4] = {};
    qk_mma(g_qc + ((size_t)b * HW_ + w) * CQ_,
           g_kc + ((size_t)b * HW_ + w) * CQ_,
           (size_t)W_ * CQ_, sm, acc);
    float* Es = (float*)sm;  // [128][132]
    #pragma unroll
    for (int i = 0; i < 2; ++i)
        #pragma unroll
        for (int j = 0; j < 4; ++j) {
            int row = wr * 32 + i * 16 + gid;
            int col = wc * 32 + j * 8 + tig * 2;
            Es[row * 132 + col]           = (row == col)         ? NEGF : acc[i][j][0];
            Es[row * 132 + col + 1]       = (row == col + 1)     ? NEGF : acc[i][j][1];
            Es[(row + 8) * 132 + col]     = (row + 8 == col)     ? NEGF : acc[i][j][2];
            Es[(row + 8) * 132 + col + 1] = (row + 8 == col + 1) ? NEGF : acc[i][j][3];
        }
    __syncthreads();
    #pragma unroll
    for (int grp = 0; grp < 4; ++grp) {
        float v[2][4];
        int rr[2];
        #pragma unroll
        for (int s = 0; s < 2; ++s) {
            rr[s] = wid5 + 16 * (grp * 2 + s);
            float4 x = *(const float4*)&Es[rr[s] * 132 + lane * 4];
            v[s][0] = x.x; v[s][1] = x.y; v[s][2] = x.z; v[s][3] = x.w;
        }
        float thr[2];
        topk64x2(v, thr);
        #pragma unroll
        for (int s = 0; s < 2; ++s) {
            float4 o;
            o.x = v[s][0] >= thr[s] ? v[s][0] : NEGF;
            o.y = v[s][1] >= thr[s] ? v[s][1] : NEGF;
            o.z = v[s][2] >= thr[s] ? v[s][2] : NEGF;
            o.w = v[s][3] >= thr[s] ? v[s][3] : NEGF;
            *(float4*)(g_att + (((size_t)b * H_ + rr[s]) * W_ + w) * 256 + lane * 4) = o;
        }
    }
}

// ---------------- transpose body: 64x64 tile ----------------------------------
__device__ __forceinline__ void transpose_body(int n, int w0, int h0, float* sm)
{
    float* tile = sm;
    const float* s = g_v  + (size_t)n * HW_;
    float*       d = g_vt + (size_t)n * HW_;
    const int t = threadIdx.x;
    const int col = t & 63, rg = t >> 6;
    #pragma unroll
    for (int i = 0; i < 8; ++i) {
        int row = rg + i * 8;
        tile[row * 65 + col] = s[(size_t)(h0 + row) * W_ + w0 + col];
    }
    __syncthreads();
    #pragma unroll
    for (int i = 0; i < 8; ++i) {
        int row = rg + i * 8;
        d[(size_t)(w0 + row) * H_ + h0 + col] = tile[col * 65 + row];
    }
}

// ---------------- K2: eH + v-transpose fused (2 CTAs/SM) ---------------------
__global__ void __launch_bounds__(512, 2) k2_eH_tr()
{
    extern __shared__ __align__(16) char smc[];
    const int id = blockIdx.x;
    if (id < 1024) {
        eH_body(id & 127, id >> 7, smc);
    } else {
        int r = id - 1024;
        transpose_body(r >> 2, (r & 1) * 64, ((r >> 1) & 1) * 64, (float*)smc);
    }
}

// ---------------- K3: eW (mma) + joint softmax (2 CTAs/SM) --------------------
__global__ void __launch_bounds__(512, 2) k3_eW_softmax()
{
    extern __shared__ __align__(16) char smc[];
    const int h = blockIdx.x & 127, b = blockIdx.x >> 7;
    const int t = threadIdx.x, wid5 = t >> 5, lane = t & 31;
    const int gid = lane >> 2, tig = lane & 3;
    const int wr = wid5 & 3, wc = wid5 >> 2;
    float acc[2][4][4] = {};
    qk_mma(g_qc + ((size_t)b * HW_ + (size_t)h * W_) * CQ_,
           g_kc + ((size_t)b * HW_ + (size_t)h * W_) * CQ_,
           (size_t)CQ_, smc, acc);
    float* Es = (float*)smc;  // [128][132]
    #pragma unroll
    for (int i = 0; i < 2; ++i)
        #pragma unroll
        for (int j = 0; j < 4; ++j) {
            int row = wr * 32 + i * 16 + gid;
            int col = wc * 32 + j * 8 + tig * 2;
            *(float2*)&Es[row * 132 + col]       = make_float2(acc[i][j][0], acc[i][j][1]);
            *(float2*)&Es[(row + 8) * 132 + col] = make_float2(acc[i][j][2], acc[i][j][3]);
        }
    __syncthreads();
    #pragma unroll
    for (int grp = 0; grp < 4; ++grp) {
        float wv[2][4];
        int rr[2];
        #pragma unroll
        for (int s = 0; s < 2; ++s) {
            rr[s] = wid5 + 16 * (grp * 2 + s);
            float4 x = *(const float4*)&Es[rr[s] * 132 + lane * 4];
            wv[s][0] = x.x; wv[s][1] = x.y; wv[s][2] = x.z; wv[s][3] = x.w;
        }
        float thr[2];
        topk64x2(wv, thr);
        float hv[2][4];
        #pragma unroll
        for (int s = 0; s < 2; ++s) {
            #pragma unroll
            for (int j = 0; j < 4; ++j)
                wv[s][j] = (wv[s][j] >= thr[s]) ? wv[s][j] : NEGF;
            float4 x = *(const float4*)(g_att + (((size_t)b * H_ + h) * W_ + rr[s]) * 256 + lane * 4);
            hv[s][0] = x.x; hv[s][1] = x.y; hv[s][2] = x.z; hv[s][3] = x.w;
        }
        float m[2];
        #pragma unroll
        for (int s = 0; s < 2; ++s) {
            m[s] = NEGF;
            #pragma unroll
            for (int j = 0; j < 4; ++j) m[s] = fmaxf(m[s], fmaxf(wv[s][j], hv[s][j]));
        }
        #pragma unroll
        for (int off = 16; off; off >>= 1)
            #pragma unroll
            for (int s = 0; s < 2; ++s)
                m[s] = fmaxf(m[s], __shfl_xor_sync(0xffffffffu, m[s], off));
        float ph[2][4], pw[2][4], sum[2];
        #pragma unroll
        for (int s = 0; s < 2; ++s) {
            sum[s] = 0.f;
            #pragma unroll
            for (int j = 0; j < 4; ++j) {
                ph[s][j] = __expf(hv[s][j] - m[s]);
                pw[s][j] = __expf(wv[s][j] - m[s]);
                sum[s] += ph[s][j] + pw[s][j];
            }
        }
        #pragma unroll
        for (int off = 16; off; off >>= 1)
            #pragma unroll
            for (int s = 0; s < 2; ++s)
                sum[s] += __shfl_xor_sync(0xffffffffu, sum[s], off);
        #pragma unroll
        for (int s = 0; s < 2; ++s) {
            float inv = 1.0f / sum[s];
            float* arow = g_att + (((size_t)b * H_ + h) * W_ + rr[s]) * 256;
            *(float4*)(arow + lane * 4) =
                make_float4(ph[s][0]*inv, ph[s][1]*inv, ph[s][2]*inv, ph[s][3]*inv);
            *(float4*)(arow + 128 + lane * 4) =
                make_float4(pw[s][0]*inv, pw[s][1]*inv, pw[s][2]*inv, pw[s][3]*inv);
        }
    }
}

// ---------------- K4: AV GEMM via mma, c-tile 64, 2 CTAs/SM ------------------
template<bool HSIDE>
__device__ __forceinline__ void av_mma_body(int c0, int p, int b, char* sm)
{
    const int t = threadIdx.x, wid = t >> 5, lane = t & 31;
    const int gid = lane >> 2, tig = lane & 3;
    const int wr = wid & 3, wc = wid >> 2;   // warp tile: 16 c x 32 x

    const float* vbase = HSIDE ? g_vt + (((size_t)b * C_ + c0) * W_ + p) * H_
                               : g_v  + (((size_t)b * C_ + c0) * H_ + p) * W_;
    const float* abase = HSIDE ? g_att + ((size_t)b * HW_ + p) * 256
                               : g_att + (((size_t)b * H_ + p) * W_) * 256 + 128;
    const size_t astride = HSIDE ? (size_t)W_ * 256 : 256;

    #pragma unroll
    for (int i = 0; i < 4; ++i) {            // V: 64x128 = 2048 float4
        int idx = t + i * 512;
        int r = idx >> 5, g4 = (idx & 31) * 4;
        st_split(sm + K4_V + r * RSK + g4 * 4,
                 *(const float4*)(vbase + (size_t)r * HW_ + g4));
    }
    #pragma unroll
    for (int i = 0; i < 8; ++i) {            // A: 128x128 = 4096 float4
        int idx = t + i * 512;
        int r = idx >> 5, g4 = (idx & 31) * 4;
        st_split(sm + K4_A + r * RSK + g4 * 4,
                 *(const float4*)(abase + (size_t)r * astride + g4));
    }
    __syncthreads();

    float acc[4][4] = {};
    #pragma unroll
    for (int ks = 0; ks < 8; ++ks) {
        const int k0 = ks * 16;
        unsigned aH[4], aL[4];
        ldfragA2(sm, K4_V, wr * 16, k0, gid, tig, RSK, aH, aL);
        #pragma unroll
        for (int j = 0; j < 4; ++j) {
            unsigned bH[2], bL[2];
            ldfragB2(sm, K4_A, wc * 32 + j * 8, k0, gid, tig, RSK, bH, bL);
            mma16816(acc[j], aH, bH);
            mma16816(acc[j], aH, bL);
            mma16816(acc[j], aL, bH);
        }
    }
    __syncthreads();

    float* stage = (float*)sm;   // [64][132]
    #pragma unroll
    for (int j = 0; j < 4; ++j) {
        int row = wr * 16 + gid;
        int col = wc * 32 + j * 8 + tig * 2;
        *(float2*)&stage[row * 132 + col]       = make_float2(acc[j][0], acc[j][1]);
        *(float2*)&stage[(row + 8) * 132 + col] = make_float2(acc[j][2], acc[j][3]);
    }
    __syncthreads();

    float* dstbase = HSIDE ? g_oht + (((size_t)b * C_ + c0) * W_ + p) * H_
                           : g_ow  + (((size_t)b * C_ + c0) * H_ + p) * W_;
    #pragma unroll
    for (int i = 0; i < 4; ++i) {            // 64x128 = 2048 float4
        int idx = t + i * 512;
        int r = idx >> 5, x4 = (idx & 31) * 4;
        float2 u2 = *(float2*)&stage[r * 132 + x4];
        float2 w2 = *(float2*)&stage[r * 132 + x4 + 2];
        *(float4*)(dstbase + (size_t)r * HW_ + x4) = make_float4(u2.x, u2.y, w2.x, w2.y);
    }
}

__global__ void __launch_bounds__(512, 2) k4_out()
{
    extern __shared__ __align__(16) char smc[];
    int id = blockIdx.x;
    if (id < 4096) {
        av_mma_body<true >((id & 3) * 64, (id >> 2) & 127, id >> 9, smc);
    } else {
        id -= 4096;
        av_mma_body<false>((id & 3) * 64, (id >> 2) & 127, id >> 9, smc);
    }
}

// ---------------- K5: out = gamma*(outH^T + outW) + x1 -----------------------
__global__ void __launch_bounds__(256) k5_combine(
    const float* __restrict__ x1, const float* __restrict__ gamma,
    float* __restrict__ out)
{
    __shared__ float tile[32][33];
    const size_t n = blockIdx.z;
    const float* oht = g_oht + n * HW_;
    const float* ow  = g_ow  + n * HW_;
    const float* x   = x1    + n * HW_;
    float*       o   = out   + n * HW_;
    const int w0 = blockIdx.x * 32, h0 = blockIdx.y * 32;
    const int tx = threadIdx.x, ty = threadIdx.y;
    #pragma unroll
    for (int i = ty; i < 32; i += 8)
        tile[i][tx] = oht[(size_t)(w0 + i) * H_ + h0 + tx];
    __syncthreads();
    const float gm = gamma[0];
    #pragma unroll
    for (int i = ty; i < 32; i += 8) {
        size_t idx = (size_t)(h0 + i) * W_ + w0 + tx;
        o[idx] = gm * (tile[tx][i] + ow[idx]) + x[idx];
    }
}

// ---------------- launch ------------------------------------------------------
extern "C" void kernel_launch(void* const* d_in, const int* in_sizes, int n_in,
                              void* d_out, int out_size)
{
    (void)in_sizes; (void)n_in; (void)out_size;
    const float* x1    = (const float*)d_in[0];
    const float* x2    = (const float*)d_in[1];
    const float* Wq    = (const float*)d_in[2];
    const float* bq    = (const float*)d_in[3];
    const float* Wk    = (const float*)d_in[4];
    const float* bk    = (const float*)d_in[5];
    const float* Wv    = (const float*)d_in[6];
    const float* bv    = (const float*)d_in[7];
    const float* gamma = (const float*)d_in[8];
    float* out = (float*)d_out;

    cudaFuncSetAttribute(k1_proj,       cudaFuncAttributeMaxDynamicSharedMemorySize, SMEM_K1);
    cudaFuncSetAttribute(k2_eH_tr,      cudaFuncAttributeMaxDynamicSharedMemorySize, SMEM_E);
    cudaFuncSetAttribute(k3_eW_softmax, cudaFuncAttributeMaxDynamicSharedMemorySize, SMEM_E);
    cudaFuncSetAttribute(k4_out,        cudaFuncAttributeMaxDynamicSharedMemorySize, SMEM_K4);

    k1_proj      <<<6144, 512, SMEM_K1>>>(x1, x2, Wq, bq, Wk, bk, Wv, bv);
    k2_eH_tr     <<<1024 + 8192, 512, SMEM_E>>>();
    k3_eW_softmax<<<1024, 512, SMEM_E>>>();
    k4_out       <<<8192, 512, SMEM_K4>>>();
    k5_combine   <<<dim3(4, 4, B_*C_), dim3(32, 8)>>>(x1, gamma, out);
}